// round 14
// baseline (speedup 1.0000x reference)
#include <cuda_runtime.h>
#include <math.h>
#include <cstdint>

#define EPS 1e-5f
static constexpr int BATCH = 512;

// ---------------- scratch (static __device__ arrays; no allocation) ----------------
__device__ float g_x1[BATCH * 512 * 16];    // after FC+relu   (B,512,4,4)   -> gn in place
__device__ float g_x2[BATCH * 256 * 64];    // after stage0    (B,256,8,8)   -> gn in place
__device__ float g_x3[BATCH * 128 * 256];   // after stage1    (B,128,16,16) -> gn in place
__device__ float g_x4[BATCH * 64 * 1024];   // after stage2    (B,64,32,32)
__device__ float g_wq[9 * 512 * 256];       // per-quadrant transformed weights

// ---------------- per-stage config ----------------
template<int S> struct Cfg;
template<> struct Cfg<0> { static constexpr int CIN = 512, COUT = 256, HIN = 4;  };
template<> struct Cfg<1> { static constexpr int CIN = 256, COUT = 128, HIN = 8;  };
template<> struct Cfg<2> { static constexpr int CIN = 128, COUT = 64,  HIN = 16; };

template<int S> __device__ __forceinline__ float* in_ptr() {
    if constexpr (S == 0) return g_x1; else if constexpr (S == 1) return g_x2; else return g_x3;
}
template<int S> __device__ __forceinline__ float* out_ptr() {
    if constexpr (S == 0) return g_x2; else if constexpr (S == 1) return g_x3; else return g_x4;
}

// ---------------- tf32 split helpers ----------------
__device__ __forceinline__ uint32_t f2tf32(float x) {
    uint32_t u; asm("cvt.rna.tf32.f32 %0, %1;" : "=r"(u) : "f"(x)); return u;
}
__device__ __forceinline__ float2 tf32_split2(float x) {
    float hi = __uint_as_float(f2tf32(x));
    float lo = __uint_as_float(f2tf32(x - hi));
    return make_float2(hi, lo);
}
__device__ __forceinline__ void mma_tf32(float* c, const uint32_t* a, const uint32_t* b) {
    asm volatile(
        "mma.sync.aligned.m16n8k8.row.col.f32.tf32.tf32.f32 "
        "{%0,%1,%2,%3}, {%4,%5,%6,%7}, {%8,%9}, {%0,%1,%2,%3};\n"
        : "+f"(c[0]), "+f"(c[1]), "+f"(c[2]), "+f"(c[3])
        : "r"(a[0]), "r"(a[1]), "r"(a[2]), "r"(a[3]), "r"(b[0]), "r"(b[1]));
}

// float2 tile strides: stride mod 16 == 4 -> 64-bit-bank conflict-free fragment loads
static constexpr int A_ST  = 132;            // >=128, 132 % 16 == 4
static constexpr int B_ST  = 68;             // >=64,  68  % 16 == 4
static constexpr int ABUF  = 16 * A_ST;      // float2 per A buffer
static constexpr int BBUF  = 16 * B_ST;      // float2 per B buffer
static constexpr int DSM_BYTES = (2 * ABUF + 2 * BBUF) * (int)sizeof(float2);  // 51200

// ---------------- FC (1x1 over channels) + ReLU : GEMM M=8192,N=512,K=256 (split-tf32) ----------------
__global__ void __launch_bounds__(256) fc_gemm_k(const float* __restrict__ feat,
                                                 const float* __restrict__ fcw,
                                                 const float* __restrict__ fcb) {
    extern __shared__ float2 dynsm[];
    float2* Ax = dynsm;                 // [2][16][A_ST]
    float2* Bx = dynsm + 2 * ABUF;      // [2][16][B_ST]

    const int tid = threadIdx.x;
    const int m0 = blockIdx.x * 128, n0 = blockIdx.y * 64;
    const int warp = tid >> 5, lane = tid & 31;
    const int wm = warp >> 1, wn = warp & 1;
    const int tg = lane & 3, gi = lane >> 2;

    float acc[2][4][4];
#pragma unroll
    for (int mt = 0; mt < 2; mt++)
#pragma unroll
        for (int nt = 0; nt < 4; nt++)
#pragma unroll
            for (int q = 0; q < 4; q++) acc[mt][nt][q] = 0.f;

    const int lm = tid & 127, lk0 = (tid >> 7) * 8;
    const int gm = m0 + lm;
    const int b  = gm >> 4, p = gm & 15;
    const float* fb = feat + (size_t)b * 256 * 16 + p;
    const int ln = tid & 63, lkb = (tid >> 6) * 4;
    const float* bptr = fcw + (size_t)lkb * 512 + n0 + ln;

    float pa[8], pb[4];
#pragma unroll
    for (int kk = 0; kk < 8; kk++) pa[kk] = fb[(lk0 + kk) * 16];
#pragma unroll
    for (int kk = 0; kk < 4; kk++) pb[kk] = bptr[(size_t)kk * 512];

    // fill buffer 0
#pragma unroll
    for (int kk = 0; kk < 8; kk++) Ax[(lk0 + kk) * A_ST + lm] = tf32_split2(pa[kk]);
#pragma unroll
    for (int kk = 0; kk < 4; kk++) Bx[(lkb + kk) * B_ST + ln] = tf32_split2(pb[kk]);
    __syncthreads();

    int bf = 0;
    for (int kc = 0; kc < 256; kc += 16) {
        const bool more = (kc + 16 < 256);
        if (more) {
#pragma unroll
            for (int kk = 0; kk < 8; kk++) pa[kk] = fb[(kc + 16 + lk0 + kk) * 16];
            bptr += (size_t)16 * 512;
#pragma unroll
            for (int kk = 0; kk < 4; kk++) pb[kk] = bptr[(size_t)kk * 512];
        }
        const float2* Ab = Ax + bf * ABUF;
        const float2* Bb = Bx + bf * BBUF;
#pragma unroll
        for (int k8 = 0; k8 < 16; k8 += 8) {
            const int kA = k8 + tg;
            float2 a2[2][4], b2[4][2];
#pragma unroll
            for (int mt = 0; mt < 2; mt++) {
                int r = wm * 32 + mt * 16 + gi;
                const float2* Ak = Ab + kA * A_ST;
                a2[mt][0] = Ak[r];
                a2[mt][1] = Ak[r + 8];
                a2[mt][2] = Ak[4 * A_ST + r];
                a2[mt][3] = Ak[4 * A_ST + r + 8];
            }
#pragma unroll
            for (int nt = 0; nt < 4; nt++) {
                int cN = wn * 32 + nt * 8 + gi;
                const float2* Bk = Bb + kA * B_ST;
                b2[nt][0] = Bk[cN];
                b2[nt][1] = Bk[4 * B_ST + cN];
            }
            uint32_t ah[2][4], al[2][4], bh[4][2], bl[4][2];
#pragma unroll
            for (int mt = 0; mt < 2; mt++)
#pragma unroll
                for (int j = 0; j < 4; j++) {
                    ah[mt][j] = __float_as_uint(a2[mt][j].x);
                    al[mt][j] = __float_as_uint(a2[mt][j].y);
                }
#pragma unroll
            for (int nt = 0; nt < 4; nt++)
#pragma unroll
                for (int j = 0; j < 2; j++) {
                    bh[nt][j] = __float_as_uint(b2[nt][j].x);
                    bl[nt][j] = __float_as_uint(b2[nt][j].y);
                }
#pragma unroll
            for (int mt = 0; mt < 2; mt++)
#pragma unroll
                for (int nt = 0; nt < 4; nt++)
                    mma_tf32(acc[mt][nt], ah[mt], bh[nt]);
#pragma unroll
            for (int mt = 0; mt < 2; mt++)
#pragma unroll
                for (int nt = 0; nt < 4; nt++)
                    mma_tf32(acc[mt][nt], al[mt], bh[nt]);
#pragma unroll
            for (int mt = 0; mt < 2; mt++)
#pragma unroll
                for (int nt = 0; nt < 4; nt++)
                    mma_tf32(acc[mt][nt], ah[mt], bl[nt]);
        }
        if (more) {
            float2* An = Ax + (bf ^ 1) * ABUF;
            float2* Bn = Bx + (bf ^ 1) * BBUF;
#pragma unroll
            for (int kk = 0; kk < 8; kk++) An[(lk0 + kk) * A_ST + lm] = tf32_split2(pa[kk]);
#pragma unroll
            for (int kk = 0; kk < 4; kk++) Bn[(lkb + kk) * B_ST + ln] = tf32_split2(pb[kk]);
        }
        __syncthreads();
        bf ^= 1;
    }
#pragma unroll
    for (int mt = 0; mt < 2; mt++)
#pragma unroll
        for (int half = 0; half < 2; half++) {
            int gm2 = m0 + wm * 32 + mt * 16 + gi + half * 8;
            int b2i = gm2 >> 4, p2 = gm2 & 15;
#pragma unroll
            for (int nt = 0; nt < 4; nt++) {
                int n = n0 + wn * 32 + nt * 8 + tg * 2;
                float v0 = acc[mt][nt][half * 2 + 0] + fcb[n];
                float v1 = acc[mt][nt][half * 2 + 1] + fcb[n + 1];
                g_x1[((size_t)b2i * 512 + n)     * 16 + p2] = fmaxf(v0, 0.f);
                g_x1[((size_t)b2i * 512 + n + 1) * 16 + p2] = fmaxf(v1, 0.f);
            }
        }
}

// ---------------- GroupNorm(dim,dim): warp per (b,c), normalize in place ----------------
template<int S>
__global__ void __launch_bounds__(256) gn_norm_k(const float* __restrict__ gamma,
                                                 const float* __restrict__ beta) {
    constexpr int C  = Cfg<S>::CIN;
    constexpr int HW = Cfg<S>::HIN * Cfg<S>::HIN;
    constexpr int NPER = (HW + 31) / 32;
    const int wid  = blockIdx.x * 8 + (threadIdx.x >> 5);
    const int lane = threadIdx.x & 31;
    const int c = wid & (C - 1);
    float* xp = in_ptr<S>() + (size_t)wid * HW;

    float v[NPER];
    float s = 0.f, sq = 0.f;
#pragma unroll
    for (int r = 0; r < NPER; r++) {
        int p = lane + 32 * r;
        float x = 0.f;
        if (HW % 32 == 0 || p < HW) x = xp[p];
        v[r] = x; s += x; sq += x * x;
    }
#pragma unroll
    for (int o = 16; o; o >>= 1) {
        s  += __shfl_xor_sync(0xffffffffu, s, o);
        sq += __shfl_xor_sync(0xffffffffu, sq, o);
    }
    const float inv = 1.f / (float)HW;
    float mu  = s * inv;
    float var = sq * inv - mu * mu;
    float rs  = rsqrtf(var + EPS);
    float sc  = gamma[c] * rs;
    float sh  = beta[c] - mu * sc;
#pragma unroll
    for (int r = 0; r < NPER; r++) {
        int p = lane + 32 * r;
        if (HW % 32 == 0 || p < HW) xp[p] = v[r] * sc + sh;
    }
}

// ---------------- weight transform (all 4 quadrants in one launch) ----------------
template<int S>
__global__ void wtrans_all_k(const float* __restrict__ w) {
    constexpr int CIN = Cfg<S>::CIN, COUT = Cfg<S>::COUT;
    constexpr int U = CIN * COUT;
    int idx = blockIdx.x * 256 + threadIdx.x;
    if (idx >= 9 * U) return;
    int PI, PJ, rel; size_t base;
    if (idx < U)          { PI = 0; PJ = 0; base = 0;             rel = idx;         }
    else if (idx < 3 * U) { PI = 0; PJ = 1; base = (size_t)U;     rel = idx - U;     }
    else if (idx < 5 * U) { PI = 1; PJ = 0; base = (size_t)3 * U; rel = idx - 3 * U; }
    else                  { PI = 1; PJ = 1; base = (size_t)5 * U; rel = idx - 5 * U; }
    int NC = PJ + 1, T = (PI + 1) * (PJ + 1);
    int k  = rel / COUT, co = rel - k * COUT;
    int ci = k / T, tap = k - ci * T;
    int tr = tap / NC, tc = tap - tr * NC;
    int kh = PI ? 2 * tr : 1;
    int kw = PJ ? 2 * tc : 1;
    g_wq[base + rel] = w[(size_t)(co * CIN + ci) * 9 + kh * 3 + kw];
}

// ---------------- fused deconv: all 4 quadrants via blockIdx.z (split-tf32 MMA) ----------------
// float2 (hi,lo)-interleaved, double-buffered smem: 1 barrier / 16-K slab, LDS.64 fragments.
template<int S>
__global__ void __launch_bounds__(256) deconv_all_k(const float* __restrict__ db) {
    constexpr int CIN = Cfg<S>::CIN, COUT = Cfg<S>::COUT, HIN = Cfg<S>::HIN;
    constexpr int HIN2 = HIN * HIN, HOUT = 2 * HIN;
    const int q  = blockIdx.z;                 // 0:(0,0) 1:(0,1) 2:(1,0) 3:(1,1)
    const int PI = q >> 1, PJ = q & 1;
    const int lt = PI + PJ;                    // log2(T): T = 1,2,2,4
    const int T  = 1 << lt;
    const int K  = CIN << lt;
    const size_t qbase = ((q == 0) ? 0 : (q == 1) ? 1 : (q == 2) ? 3 : 5) * (size_t)CIN * COUT;

    const float* __restrict__ xn = in_ptr<S>();
    float* __restrict__ out      = out_ptr<S>();
    const float* __restrict__ wq = g_wq + qbase;

    extern __shared__ float2 dynsm[];
    float2* Ax = dynsm;
    float2* Bx = dynsm + 2 * ABUF;

    const int tid = threadIdx.x;
    const int m0 = blockIdx.x * 128, n0 = blockIdx.y * 64;
    const int warp = tid >> 5, lane = tid & 31;
    const int wm = warp >> 1, wn = warp & 1;
    const int tg = lane & 3, gi = lane >> 2;

    float acc[2][4][4];
#pragma unroll
    for (int mt = 0; mt < 2; mt++)
#pragma unroll
        for (int nt = 0; nt < 4; nt++)
#pragma unroll
            for (int qq = 0; qq < 4; qq++) acc[mt][nt][qq] = 0.f;

    const int lm = tid & 127, lk0 = (tid >> 7) * 8;
    const int gm = m0 + lm;
    const int bb = gm / HIN2, rr = gm & (HIN2 - 1);
    const int ii = rr / HIN,  jj = rr & (HIN - 1);
    const float* xb = xn + (size_t)bb * CIN * HIN2;
    const int ln = tid & 63, lkb = (tid >> 6) * 4;

    // hoisted gather offsets (affine in kc; T | 16)
    int off[8];
    unsigned vmask = 0;
#pragma unroll
    for (int kk = 0; kk < 8; kk++) {
        int k0 = lk0 + kk;
        int ci = k0 >> lt, tap = k0 & (T - 1);
        int tr = tap >> PJ, tc = tap & PJ;
        int ih = ii + (PI ? tr : 0);
        int iw = jj + (PJ ? tc : 0);
        bool ok = (!PI || ih < HIN) && (!PJ || iw < HIN);
        vmask |= (ok ? 1u : 0u) << kk;
        off[kk] = ci * HIN2 + ih * HIN + iw;
    }
    const int dA = (16 >> lt) * HIN2;
    const float* bptr = wq + (size_t)lkb * COUT + n0 + ln;

    float pa[8], pb[4];
#pragma unroll
    for (int kk = 0; kk < 8; kk++) {
        float v = 0.f;
        if ((vmask >> kk) & 1u) v = xb[off[kk]];
        pa[kk] = v; off[kk] += dA;
    }
#pragma unroll
    for (int kk = 0; kk < 4; kk++) pb[kk] = bptr[(size_t)kk * COUT];

    // fill buffer 0
#pragma unroll
    for (int kk = 0; kk < 8; kk++) Ax[(lk0 + kk) * A_ST + lm] = tf32_split2(pa[kk]);
#pragma unroll
    for (int kk = 0; kk < 4; kk++) Bx[(lkb + kk) * B_ST + ln] = tf32_split2(pb[kk]);
    __syncthreads();

    const int nIter = K >> 4;
    int bf = 0;
    for (int it = 0; it < nIter; it++) {
        const bool more = (it + 1 < nIter);
        if (more) {
#pragma unroll
            for (int kk = 0; kk < 8; kk++) {
                float v = 0.f;
                if ((vmask >> kk) & 1u) v = xb[off[kk]];
                pa[kk] = v; off[kk] += dA;
            }
            bptr += (size_t)16 * COUT;
#pragma unroll
            for (int kk = 0; kk < 4; kk++) pb[kk] = bptr[(size_t)kk * COUT];
        }
        const float2* Ab = Ax + bf * ABUF;
        const float2* Bb = Bx + bf * BBUF;
#pragma unroll
        for (int k8 = 0; k8 < 16; k8 += 8) {
            const int kA = k8 + tg;
            float2 a2[2][4], b2[4][2];
#pragma unroll
            for (int mt = 0; mt < 2; mt++) {
                int r = wm * 32 + mt * 16 + gi;
                const float2* Ak = Ab + kA * A_ST;
                a2[mt][0] = Ak[r];
                a2[mt][1] = Ak[r + 8];
                a2[mt][2] = Ak[4 * A_ST + r];
                a2[mt][3] = Ak[4 * A_ST + r + 8];
            }
#pragma unroll
            for (int nt = 0; nt < 4; nt++) {
                int cN = wn * 32 + nt * 8 + gi;
                const float2* Bk = Bb + kA * B_ST;
                b2[nt][0] = Bk[cN];
                b2[nt][1] = Bk[4 * B_ST + cN];
            }
            uint32_t ah[2][4], al[2][4], bh[4][2], bl[4][2];
#pragma unroll
            for (int mt = 0; mt < 2; mt++)
#pragma unroll
                for (int j = 0; j < 4; j++) {
                    ah[mt][j] = __float_as_uint(a2[mt][j].x);
                    al[mt][j] = __float_as_uint(a2[mt][j].y);
                }
#pragma unroll
            for (int nt = 0; nt < 4; nt++)
#pragma unroll
                for (int j = 0; j < 2; j++) {
                    bh[nt][j] = __float_as_uint(b2[nt][j].x);
                    bl[nt][j] = __float_as_uint(b2[nt][j].y);
                }
#pragma unroll
            for (int mt = 0; mt < 2; mt++)
#pragma unroll
                for (int nt = 0; nt < 4; nt++)
                    mma_tf32(acc[mt][nt], ah[mt], bh[nt]);
#pragma unroll
            for (int mt = 0; mt < 2; mt++)
#pragma unroll
                for (int nt = 0; nt < 4; nt++)
                    mma_tf32(acc[mt][nt], al[mt], bh[nt]);
#pragma unroll
            for (int mt = 0; mt < 2; mt++)
#pragma unroll
                for (int nt = 0; nt < 4; nt++)
                    mma_tf32(acc[mt][nt], ah[mt], bl[nt]);
        }
        if (more) {
            float2* An = Ax + (bf ^ 1) * ABUF;
            float2* Bn = Bx + (bf ^ 1) * BBUF;
#pragma unroll
            for (int kk = 0; kk < 8; kk++) An[(lk0 + kk) * A_ST + lm] = tf32_split2(pa[kk]);
#pragma unroll
            for (int kk = 0; kk < 4; kk++) Bn[(lkb + kk) * B_ST + ln] = tf32_split2(pb[kk]);
        }
        __syncthreads();
        bf ^= 1;
    }
#pragma unroll
    for (int mt = 0; mt < 2; mt++)
#pragma unroll
        for (int half = 0; half < 2; half++) {
            int gm2 = m0 + wm * 32 + mt * 16 + gi + half * 8;
            int b2i = gm2 / HIN2, r2 = gm2 & (HIN2 - 1);
            int oh = 2 * (r2 / HIN) + PI;
            int ow = 2 * (r2 & (HIN - 1)) + PJ;
            float* op = out + ((size_t)b2i * COUT * HOUT + oh) * HOUT + ow;
#pragma unroll
            for (int nt = 0; nt < 4; nt++) {
                int co = n0 + wn * 32 + nt * 8 + tg * 2;
                float v0 = acc[mt][nt][half * 2 + 0] + db[co];
                float v1 = acc[mt][nt][half * 2 + 1] + db[co + 1];
                op[(size_t)co       * HOUT * HOUT] = fmaxf(v0, 0.f);
                op[(size_t)(co + 1) * HOUT * HOUT] = fmaxf(v1, 0.f);
            }
        }
}

// ---------------- head: per-channel norm (folded) + 5-step GEMV + spatial softmax ----------------
__global__ void __launch_bounds__(256) head_k(const int* __restrict__ action,
                                              const float* __restrict__ hgw,
                                              const float* __restrict__ hgb,
                                              const float* __restrict__ hcw,
                                              const float* __restrict__ hcb,
                                              float* __restrict__ out) {
    const int b = blockIdx.x;
    const int tid = threadIdx.x;
    const int lane = tid & 31, wp = tid >> 5;
    __shared__ float s_mu[64], s_rs[64];
    __shared__ float s_ws[5][64];
    __shared__ float s_bias[5];
    __shared__ float s_red[8][15];

    const float* xb = g_x4 + (size_t)b * 64 * 1024;

    for (int c = wp; c < 64; c += 8) {
        const float* xc = xb + c * 1024;
        float s = 0.f, sq = 0.f;
        for (int p = lane; p < 1024; p += 32) { float v = xc[p]; s += v; sq += v * v; }
#pragma unroll
        for (int o = 16; o; o >>= 1) {
            s  += __shfl_xor_sync(0xffffffffu, s, o);
            sq += __shfl_xor_sync(0xffffffffu, sq, o);
        }
        if (lane == 0) {
            float mu = s * (1.f / 1024.f);
            float var = sq * (1.f / 1024.f) - mu * mu;
            s_mu[c] = mu;
            s_rs[c] = rsqrtf(var + EPS);
        }
    }
    __syncthreads();

    const int a = action[b];
    for (int idx = tid; idx < 320; idx += 256) {
        int s = idx >> 6, c = idx & 63;
        s_ws[s][c] = s_rs[c] * hcw[(a * 5 + s) * 64 + c] * hgw[a * 64 + c];
    }
    __syncthreads();
    if (tid < 5) {
        float acc = hcb[a * 5 + tid];
        for (int c = 0; c < 64; c++)
            acc += hcw[(a * 5 + tid) * 64 + c] * hgb[a * 64 + c] - s_mu[c] * s_ws[tid][c];
        s_bias[tid] = acc;
    }
    __syncthreads();

    float l[5][4];
#pragma unroll
    for (int s = 0; s < 5; s++)
#pragma unroll
        for (int r = 0; r < 4; r++) l[s][r] = 0.f;
    for (int c = 0; c < 64; c++) {
        float w0 = s_ws[0][c], w1 = s_ws[1][c], w2 = s_ws[2][c], w3 = s_ws[3][c], w4 = s_ws[4][c];
#pragma unroll
        for (int r = 0; r < 4; r++) {
            float xv = xb[c * 1024 + tid + 256 * r];
            l[0][r] += xv * w0; l[1][r] += xv * w1; l[2][r] += xv * w2;
            l[3][r] += xv * w3; l[4][r] += xv * w4;
        }
    }

#pragma unroll
    for (int s = 0; s < 5; s++) {
        float m = -1e30f;
#pragma unroll
        for (int r = 0; r < 4; r++) { l[s][r] += s_bias[s]; m = fmaxf(m, l[s][r]); }
#pragma unroll
        for (int o = 16; o; o >>= 1) m = fmaxf(m, __shfl_xor_sync(0xffffffffu, m, o));
        if (lane == 0) s_red[wp][s] = m;
    }
    __syncthreads();
    float mx[5];
#pragma unroll
    for (int s = 0; s < 5; s++) {
        float m = s_red[0][s];
#pragma unroll
        for (int w2 = 1; w2 < 8; w2++) m = fmaxf(m, s_red[w2][s]);
        mx[s] = m;
    }
    __syncthreads();

    float part[15];
#pragma unroll
    for (int s = 0; s < 5; s++) {
        float se = 0.f, sx = 0.f, sy = 0.f;
#pragma unroll
        for (int r = 0; r < 4; r++) {
            int p = tid + 256 * r;
            float e  = expf(l[s][r] - mx[s]);
            float xs = -1.f + (2.f / 31.f) * (float)(p & 31);
            float ys = -1.f + (2.f / 31.f) * (float)(p >> 5);
            se += e; sx += e * xs; sy += e * ys;
        }
        part[3 * s] = se; part[3 * s + 1] = sx; part[3 * s + 2] = sy;
    }
#pragma unroll
    for (int qq = 0; qq < 15; qq++)
#pragma unroll
        for (int o = 16; o; o >>= 1) part[qq] += __shfl_xor_sync(0xffffffffu, part[qq], o);
    if (lane == 0) {
#pragma unroll
        for (int qq = 0; qq < 15; qq++) s_red[wp][qq] = part[qq];
    }
    __syncthreads();
    if (tid < 5) {
        float se = 0.f, sx = 0.f, sy = 0.f;
        for (int w2 = 0; w2 < 8; w2++) {
            se += s_red[w2][3 * tid];
            sx += s_red[w2][3 * tid + 1];
            sy += s_red[w2][3 * tid + 2];
        }
        out[b * 10 + tid * 2 + 0] = sx / se;
        out[b * 10 + tid * 2 + 1] = sy / se;
    }
}

// ---------------- host-side stage driver ----------------
template<int S>
static void run_stage(const float* gw, const float* gb, const float* dw, const float* db) {
    constexpr int CIN = Cfg<S>::CIN, COUT = Cfg<S>::COUT, HIN = Cfg<S>::HIN;
    gn_norm_k<S><<<(BATCH * CIN) / 8, 256>>>(gw, gb);
    wtrans_all_k<S><<<(9 * CIN * COUT + 255) / 256, 256>>>(dw);
    constexpr int M = BATCH * HIN * HIN;
    dim3 g(M / 128, COUT / 64, 4);
    cudaFuncSetAttribute(deconv_all_k<S>, cudaFuncAttributeMaxDynamicSharedMemorySize, DSM_BYTES);
    deconv_all_k<S><<<g, 256, DSM_BYTES>>>(db);
}

extern "C" void kernel_launch(void* const* d_in, const int* in_sizes, int n_in,
                              void* d_out, int out_size) {
    (void)in_sizes; (void)n_in; (void)out_size;
    const float* feat   = (const float*)d_in[0];
    const int*   action = (const int*)  d_in[1];
    // d_in[2] = scene_idx (unused by reference)
    const float* fcw = (const float*)d_in[3];
    const float* fcb = (const float*)d_in[4];
    const float* gw0 = (const float*)d_in[5];  const float* gb0 = (const float*)d_in[6];
    const float* dw0 = (const float*)d_in[7];  const float* db0 = (const float*)d_in[8];
    const float* gw1 = (const float*)d_in[9];  const float* gb1 = (const float*)d_in[10];
    const float* dw1 = (const float*)d_in[11]; const float* db1 = (const float*)d_in[12];
    const float* gw2 = (const float*)d_in[13]; const float* gb2 = (const float*)d_in[14];
    const float* dw2 = (const float*)d_in[15]; const float* db2 = (const float*)d_in[16];
    const float* hgw = (const float*)d_in[17]; const float* hgb = (const float*)d_in[18];
    const float* hcw = (const float*)d_in[19]; const float* hcb = (const float*)d_in[20];
    float* out = (float*)d_out;

    cudaFuncSetAttribute(fc_gemm_k, cudaFuncAttributeMaxDynamicSharedMemorySize, DSM_BYTES);
    fc_gemm_k<<<dim3(64, 8), 256, DSM_BYTES>>>(feat, fcw, fcb);
    run_stage<0>(gw0, gb0, dw0, db0);
    run_stage<1>(gw1, gb1, dw1, db1);
    run_stage<2>(gw2, gb2, dw2, db2);
    head_k<<<BATCH, 256>>>(action, hgw, hgb, hcw, hcb, out);
}

// round 15
// speedup vs baseline: 1.0614x; 1.0614x over previous
#include <cuda_runtime.h>
#include <math.h>
#include <cstdint>

#define EPS 1e-5f
static constexpr int BATCH = 512;

// ---------------- scratch (static __device__ arrays; no allocation) ----------------
__device__ float  g_x1 [BATCH * 512 * 16];    // after FC+relu   (raw)
__device__ float  g_x2 [BATCH * 256 * 64];    // after stage0    (raw)
__device__ float  g_x3 [BATCH * 128 * 256];   // after stage1    (raw)
__device__ float  g_x4 [BATCH * 64 * 1024];   // after stage2    (raw, head input)
__device__ float2 g_x1s[BATCH * 512 * 16];    // gn-normalized, tf32-split (hi,lo)
__device__ float2 g_x2s[BATCH * 256 * 64];
__device__ float2 g_x3s[BATCH * 128 * 256];
__device__ float2 g_wqs[9 * 512 * 256];       // per-quadrant transformed weights, split

// ---------------- per-stage config ----------------
template<int S> struct Cfg;
template<> struct Cfg<0> { static constexpr int CIN = 512, COUT = 256, HIN = 4;  };
template<> struct Cfg<1> { static constexpr int CIN = 256, COUT = 128, HIN = 8;  };
template<> struct Cfg<2> { static constexpr int CIN = 128, COUT = 64,  HIN = 16; };

template<int S> __device__ __forceinline__ float* inraw_ptr() {
    if constexpr (S == 0) return g_x1; else if constexpr (S == 1) return g_x2; else return g_x3;
}
template<int S> __device__ __forceinline__ float2* ins_ptr() {
    if constexpr (S == 0) return g_x1s; else if constexpr (S == 1) return g_x2s; else return g_x3s;
}
template<int S> __device__ __forceinline__ float* out_ptr() {
    if constexpr (S == 0) return g_x2; else if constexpr (S == 1) return g_x3; else return g_x4;
}

// ---------------- tf32 split helpers ----------------
__device__ __forceinline__ uint32_t f2tf32(float x) {
    uint32_t u; asm("cvt.rna.tf32.f32 %0, %1;" : "=r"(u) : "f"(x)); return u;
}
__device__ __forceinline__ float2 tf32_split2(float x) {
    float hi = __uint_as_float(f2tf32(x));
    float lo = __uint_as_float(f2tf32(x - hi));
    return make_float2(hi, lo);
}
__device__ __forceinline__ void mma_tf32(float* c, const uint32_t* a, const uint32_t* b) {
    asm volatile(
        "mma.sync.aligned.m16n8k8.row.col.f32.tf32.tf32.f32 "
        "{%0,%1,%2,%3}, {%4,%5,%6,%7}, {%8,%9}, {%0,%1,%2,%3};\n"
        : "+f"(c[0]), "+f"(c[1]), "+f"(c[2]), "+f"(c[3])
        : "r"(a[0]), "r"(a[1]), "r"(a[2]), "r"(a[3]), "r"(b[0]), "r"(b[1]));
}

// float2 tile strides: stride mod 16 == 4 -> conflict-free 64-bit-bank fragment loads
static constexpr int A_ST = 132;   // >=128
static constexpr int B_ST = 68;    // >=64
// static smem: (16*132 + 16*68) float2 = 25600 B

// ---------------- FC (1x1 over channels) + ReLU : GEMM M=8192,N=512,K=256 (split-tf32) ----------------
__global__ void __launch_bounds__(256) fc_gemm_k(const float* __restrict__ feat,
                                                 const float* __restrict__ fcw,
                                                 const float* __restrict__ fcb) {
    __shared__ float2 Ax[16][A_ST];
    __shared__ float2 Bx[16][B_ST];
    const int tid = threadIdx.x;
    const int m0 = blockIdx.x * 128, n0 = blockIdx.y * 64;
    const int warp = tid >> 5, lane = tid & 31;
    const int wm = warp >> 1, wn = warp & 1;
    const int tg = lane & 3, gi = lane >> 2;

    float acc[2][4][4];
#pragma unroll
    for (int mt = 0; mt < 2; mt++)
#pragma unroll
        for (int nt = 0; nt < 4; nt++)
#pragma unroll
            for (int q = 0; q < 4; q++) acc[mt][nt][q] = 0.f;

    const int lm = tid & 127, lk0 = (tid >> 7) * 8;
    const int gm = m0 + lm;
    const int b  = gm >> 4, p = gm & 15;
    const float* fb = feat + (size_t)b * 256 * 16 + p;
    const int ln = tid & 63, lkb = (tid >> 6) * 4;
    const float* bptr = fcw + (size_t)lkb * 512 + n0 + ln;

    float pa[8], pb[4];
#pragma unroll
    for (int kk = 0; kk < 8; kk++) pa[kk] = fb[(lk0 + kk) * 16];
#pragma unroll
    for (int kk = 0; kk < 4; kk++) pb[kk] = bptr[(size_t)kk * 512];

    for (int kc = 0; kc < 256; kc += 16) {
#pragma unroll
        for (int kk = 0; kk < 8; kk++) Ax[lk0 + kk][lm] = tf32_split2(pa[kk]);
#pragma unroll
        for (int kk = 0; kk < 4; kk++) Bx[lkb + kk][ln] = tf32_split2(pb[kk]);
        __syncthreads();
        if (kc + 16 < 256) {
#pragma unroll
            for (int kk = 0; kk < 8; kk++) pa[kk] = fb[(kc + 16 + lk0 + kk) * 16];
            bptr += (size_t)16 * 512;
#pragma unroll
            for (int kk = 0; kk < 4; kk++) pb[kk] = bptr[(size_t)kk * 512];
        }
#pragma unroll
        for (int k8 = 0; k8 < 16; k8 += 8) {
            const int kA = k8 + tg;
            float2 a2[2][4], b2[4][2];
#pragma unroll
            for (int mt = 0; mt < 2; mt++) {
                int r = wm * 32 + mt * 16 + gi;
                a2[mt][0] = Ax[kA][r];
                a2[mt][1] = Ax[kA][r + 8];
                a2[mt][2] = Ax[kA + 4][r];
                a2[mt][3] = Ax[kA + 4][r + 8];
            }
#pragma unroll
            for (int nt = 0; nt < 4; nt++) {
                int cN = wn * 32 + nt * 8 + gi;
                b2[nt][0] = Bx[kA][cN];
                b2[nt][1] = Bx[kA + 4][cN];
            }
            uint32_t ah[2][4], al[2][4], bh[4][2], bl[4][2];
#pragma unroll
            for (int mt = 0; mt < 2; mt++)
#pragma unroll
                for (int j = 0; j < 4; j++) {
                    ah[mt][j] = __float_as_uint(a2[mt][j].x);
                    al[mt][j] = __float_as_uint(a2[mt][j].y);
                }
#pragma unroll
            for (int nt = 0; nt < 4; nt++)
#pragma unroll
                for (int j = 0; j < 2; j++) {
                    bh[nt][j] = __float_as_uint(b2[nt][j].x);
                    bl[nt][j] = __float_as_uint(b2[nt][j].y);
                }
#pragma unroll
            for (int mt = 0; mt < 2; mt++)
#pragma unroll
                for (int nt = 0; nt < 4; nt++) {
                    mma_tf32(acc[mt][nt], al[mt], bh[nt]);
                    mma_tf32(acc[mt][nt], ah[mt], bl[nt]);
                    mma_tf32(acc[mt][nt], ah[mt], bh[nt]);
                }
        }
        __syncthreads();
    }
#pragma unroll
    for (int mt = 0; mt < 2; mt++)
#pragma unroll
        for (int half = 0; half < 2; half++) {
            int gm2 = m0 + wm * 32 + mt * 16 + gi + half * 8;
            int b2i = gm2 >> 4, p2 = gm2 & 15;
#pragma unroll
            for (int nt = 0; nt < 4; nt++) {
                int n = n0 + wn * 32 + nt * 8 + tg * 2;
                float v0 = acc[mt][nt][half * 2 + 0] + fcb[n];
                float v1 = acc[mt][nt][half * 2 + 1] + fcb[n + 1];
                g_x1[((size_t)b2i * 512 + n)     * 16 + p2] = fmaxf(v0, 0.f);
                g_x1[((size_t)b2i * 512 + n + 1) * 16 + p2] = fmaxf(v1, 0.f);
            }
        }
}

// ---------------- GroupNorm: warp per (b,c); writes tf32-split float2 ----------------
template<int S>
__global__ void __launch_bounds__(256) gn_norm_k(const float* __restrict__ gamma,
                                                 const float* __restrict__ beta) {
    constexpr int C  = Cfg<S>::CIN;
    constexpr int HW = Cfg<S>::HIN * Cfg<S>::HIN;
    constexpr int NPER = (HW + 31) / 32;
    const int wid  = blockIdx.x * 8 + (threadIdx.x >> 5);
    const int lane = threadIdx.x & 31;
    const int c = wid & (C - 1);
    const float* xp = inraw_ptr<S>() + (size_t)wid * HW;
    float2* xs = ins_ptr<S>() + (size_t)wid * HW;

    float v[NPER];
    float s = 0.f, sq = 0.f;
#pragma unroll
    for (int r = 0; r < NPER; r++) {
        int p = lane + 32 * r;
        float x = 0.f;
        if (HW % 32 == 0 || p < HW) x = xp[p];
        v[r] = x; s += x; sq += x * x;
    }
#pragma unroll
    for (int o = 16; o; o >>= 1) {
        s  += __shfl_xor_sync(0xffffffffu, s, o);
        sq += __shfl_xor_sync(0xffffffffu, sq, o);
    }
    const float inv = 1.f / (float)HW;
    float mu  = s * inv;
    float var = sq * inv - mu * mu;
    float rs  = rsqrtf(var + EPS);
    float sc  = gamma[c] * rs;
    float sh  = beta[c] - mu * sc;
#pragma unroll
    for (int r = 0; r < NPER; r++) {
        int p = lane + 32 * r;
        if (HW % 32 == 0 || p < HW) xs[p] = tf32_split2(v[r] * sc + sh);
    }
}

// ---------------- weight transform: writes tf32-split float2 ----------------
template<int S>
__global__ void wtrans_all_k(const float* __restrict__ w) {
    constexpr int CIN = Cfg<S>::CIN, COUT = Cfg<S>::COUT;
    constexpr int U = CIN * COUT;
    int idx = blockIdx.x * 256 + threadIdx.x;
    if (idx >= 9 * U) return;
    int PI, PJ, rel; size_t base;
    if (idx < U)          { PI = 0; PJ = 0; base = 0;             rel = idx;         }
    else if (idx < 3 * U) { PI = 0; PJ = 1; base = (size_t)U;     rel = idx - U;     }
    else if (idx < 5 * U) { PI = 1; PJ = 0; base = (size_t)3 * U; rel = idx - 3 * U; }
    else                  { PI = 1; PJ = 1; base = (size_t)5 * U; rel = idx - 5 * U; }
    int NC = PJ + 1, T = (PI + 1) * (PJ + 1);
    int k  = rel / COUT, co = rel - k * COUT;
    int ci = k / T, tap = k - ci * T;
    int tr = tap / NC, tc = tap - tr * NC;
    int kh = PI ? 2 * tr : 1;
    int kw = PJ ? 2 * tc : 1;
    g_wqs[base + rel] = tf32_split2(w[(size_t)(co * CIN + ci) * 9 + kh * 3 + kw]);
}

// ---------------- fused deconv: all 4 quadrants via blockIdx.z (split-tf32 MMA) ----------------
// Pre-split operands: fill loop is a pure copy; inner loop is LDS.64 + MMA only.
template<int S>
__global__ void __launch_bounds__(256) deconv_all_k(const float* __restrict__ db) {
    constexpr int CIN = Cfg<S>::CIN, COUT = Cfg<S>::COUT, HIN = Cfg<S>::HIN;
    constexpr int HIN2 = HIN * HIN, HOUT = 2 * HIN;
    const int q  = blockIdx.z;                 // 0:(0,0) 1:(0,1) 2:(1,0) 3:(1,1)
    const int PI = q >> 1, PJ = q & 1;
    const int lt = PI + PJ;                    // log2(T): T = 1,2,2,4
    const int T  = 1 << lt;
    const int K  = CIN << lt;
    const size_t qbase = ((q == 0) ? 0 : (q == 1) ? 1 : (q == 2) ? 3 : 5) * (size_t)CIN * COUT;

    const float2* __restrict__ xn = ins_ptr<S>();
    float* __restrict__ out       = out_ptr<S>();
    const float2* __restrict__ wq = g_wqs + qbase;

    __shared__ float2 Ax[16][A_ST];
    __shared__ float2 Bx[16][B_ST];
    const int tid = threadIdx.x;
    const int m0 = blockIdx.x * 128, n0 = blockIdx.y * 64;
    const int warp = tid >> 5, lane = tid & 31;
    const int wm = warp >> 1, wn = warp & 1;
    const int tg = lane & 3, gi = lane >> 2;

    float acc[2][4][4];
#pragma unroll
    for (int mt = 0; mt < 2; mt++)
#pragma unroll
        for (int nt = 0; nt < 4; nt++)
#pragma unroll
            for (int qq = 0; qq < 4; qq++) acc[mt][nt][qq] = 0.f;

    const int lm = tid & 127, lk0 = (tid >> 7) * 8;
    const int gm = m0 + lm;
    const int bb = gm / HIN2, rr = gm & (HIN2 - 1);
    const int ii = rr / HIN,  jj = rr & (HIN - 1);
    const float2* xb = xn + (size_t)bb * CIN * HIN2;
    const int ln = tid & 63, lkb = (tid >> 6) * 4;

    // hoisted gather offsets (affine in kc; T | 16)
    int off[8];
    unsigned vmask = 0;
#pragma unroll
    for (int kk = 0; kk < 8; kk++) {
        int k0 = lk0 + kk;
        int ci = k0 >> lt, tap = k0 & (T - 1);
        int tr = tap >> PJ, tc = tap & PJ;
        int ih = ii + (PI ? tr : 0);
        int iw = jj + (PJ ? tc : 0);
        bool ok = (!PI || ih < HIN) && (!PJ || iw < HIN);
        vmask |= (ok ? 1u : 0u) << kk;
        off[kk] = ci * HIN2 + ih * HIN + iw;
    }
    const int dA = (16 >> lt) * HIN2;
    const float2* bptr = wq + (size_t)lkb * COUT + n0 + ln;

    float2 pa[8], pb[4];
#pragma unroll
    for (int kk = 0; kk < 8; kk++) {
        float2 v = make_float2(0.f, 0.f);
        if ((vmask >> kk) & 1u) v = xb[off[kk]];
        pa[kk] = v; off[kk] += dA;
    }
#pragma unroll
    for (int kk = 0; kk < 4; kk++) pb[kk] = bptr[(size_t)kk * COUT];

    const int nIter = K >> 4;
    for (int it = 0; it < nIter; it++) {
#pragma unroll
        for (int kk = 0; kk < 8; kk++) Ax[lk0 + kk][lm] = pa[kk];
#pragma unroll
        for (int kk = 0; kk < 4; kk++) Bx[lkb + kk][ln] = pb[kk];
        __syncthreads();
        if (it + 1 < nIter) {
#pragma unroll
            for (int kk = 0; kk < 8; kk++) {
                float2 v = make_float2(0.f, 0.f);
                if ((vmask >> kk) & 1u) v = xb[off[kk]];
                pa[kk] = v; off[kk] += dA;
            }
            bptr += (size_t)16 * COUT;
#pragma unroll
            for (int kk = 0; kk < 4; kk++) pb[kk] = bptr[(size_t)kk * COUT];
        }
#pragma unroll
        for (int k8 = 0; k8 < 16; k8 += 8) {
            const int kA = k8 + tg;
            float2 a2[2][4], b2[4][2];
#pragma unroll
            for (int mt = 0; mt < 2; mt++) {
                int r = wm * 32 + mt * 16 + gi;
                a2[mt][0] = Ax[kA][r];
                a2[mt][1] = Ax[kA][r + 8];
                a2[mt][2] = Ax[kA + 4][r];
                a2[mt][3] = Ax[kA + 4][r + 8];
            }
#pragma unroll
            for (int nt = 0; nt < 4; nt++) {
                int cN = wn * 32 + nt * 8 + gi;
                b2[nt][0] = Bx[kA][cN];
                b2[nt][1] = Bx[kA + 4][cN];
            }
            uint32_t ah[2][4], al[2][4], bh[4][2], bl[4][2];
#pragma unroll
            for (int mt = 0; mt < 2; mt++)
#pragma unroll
                for (int j = 0; j < 4; j++) {
                    ah[mt][j] = __float_as_uint(a2[mt][j].x);
                    al[mt][j] = __float_as_uint(a2[mt][j].y);
                }
#pragma unroll
            for (int nt = 0; nt < 4; nt++)
#pragma unroll
                for (int j = 0; j < 2; j++) {
                    bh[nt][j] = __float_as_uint(b2[nt][j].x);
                    bl[nt][j] = __float_as_uint(b2[nt][j].y);
                }
#pragma unroll
            for (int mt = 0; mt < 2; mt++)
#pragma unroll
                for (int nt = 0; nt < 4; nt++) {
                    mma_tf32(acc[mt][nt], al[mt], bh[nt]);
                    mma_tf32(acc[mt][nt], ah[mt], bl[nt]);
                    mma_tf32(acc[mt][nt], ah[mt], bh[nt]);
                }
        }
        __syncthreads();
    }
#pragma unroll
    for (int mt = 0; mt < 2; mt++)
#pragma unroll
        for (int half = 0; half < 2; half++) {
            int gm2 = m0 + wm * 32 + mt * 16 + gi + half * 8;
            int b2i = gm2 / HIN2, r2 = gm2 & (HIN2 - 1);
            int oh = 2 * (r2 / HIN) + PI;
            int ow = 2 * (r2 & (HIN - 1)) + PJ;
            float* op = out + ((size_t)b2i * COUT * HOUT + oh) * HOUT + ow;
#pragma unroll
            for (int nt = 0; nt < 4; nt++) {
                int co = n0 + wn * 32 + nt * 8 + tg * 2;
                float v0 = acc[mt][nt][half * 2 + 0] + db[co];
                float v1 = acc[mt][nt][half * 2 + 1] + db[co + 1];
                op[(size_t)co       * HOUT * HOUT] = fmaxf(v0, 0.f);
                op[(size_t)(co + 1) * HOUT * HOUT] = fmaxf(v1, 0.f);
            }
        }
}

// ---------------- head: per-channel norm (folded) + 5-step GEMV + spatial softmax ----------------
__global__ void __launch_bounds__(256) head_k(const int* __restrict__ action,
                                              const float* __restrict__ hgw,
                                              const float* __restrict__ hgb,
                                              const float* __restrict__ hcw,
                                              const float* __restrict__ hcb,
                                              float* __restrict__ out) {
    const int b = blockIdx.x;
    const int tid = threadIdx.x;
    const int lane = tid & 31, wp = tid >> 5;
    __shared__ float s_mu[64], s_rs[64];
    __shared__ float s_ws[5][64];
    __shared__ float s_bias[5];
    __shared__ float s_red[8][15];

    const float* xb = g_x4 + (size_t)b * 64 * 1024;

    for (int c = wp; c < 64; c += 8) {
        const float* xc = xb + c * 1024;
        float s = 0.f, sq = 0.f;
        for (int p = lane; p < 1024; p += 32) { float v = xc[p]; s += v; sq += v * v; }
#pragma unroll
        for (int o = 16; o; o >>= 1) {
            s  += __shfl_xor_sync(0xffffffffu, s, o);
            sq += __shfl_xor_sync(0xffffffffu, sq, o);
        }
        if (lane == 0) {
            float mu = s * (1.f / 1024.f);
            float var = sq * (1.f / 1024.f) - mu * mu;
            s_mu[c] = mu;
            s_rs[c] = rsqrtf(var + EPS);
        }
    }
    __syncthreads();

    const int a = action[b];
    for (int idx = tid; idx < 320; idx += 256) {
        int s = idx >> 6, c = idx & 63;
        s_ws[s][c] = s_rs[c] * hcw[(a * 5 + s) * 64 + c] * hgw[a * 64 + c];
    }
    __syncthreads();
    if (tid < 5) {
        float acc = hcb[a * 5 + tid];
        for (int c = 0; c < 64; c++)
            acc += hcw[(a * 5 + tid) * 64 + c] * hgb[a * 64 + c] - s_mu[c] * s_ws[tid][c];
        s_bias[tid] = acc;
    }
    __syncthreads();

    float l[5][4];
#pragma unroll
    for (int s = 0; s < 5; s++)
#pragma unroll
        for (int r = 0; r < 4; r++) l[s][r] = 0.f;
    for (int c = 0; c < 64; c++) {
        float w0 = s_ws[0][c], w1 = s_ws[1][c], w2 = s_ws[2][c], w3 = s_ws[3][c], w4 = s_ws[4][c];
#pragma unroll
        for (int r = 0; r < 4; r++) {
            float xv = xb[c * 1024 + tid + 256 * r];
            l[0][r] += xv * w0; l[1][r] += xv * w1; l[2][r] += xv * w2;
            l[3][r] += xv * w3; l[4][r] += xv * w4;
        }
    }

#pragma unroll
    for (int s = 0; s < 5; s++) {
        float m = -1e30f;
#pragma unroll
        for (int r = 0; r < 4; r++) { l[s][r] += s_bias[s]; m = fmaxf(m, l[s][r]); }
#pragma unroll
        for (int o = 16; o; o >>= 1) m = fmaxf(m, __shfl_xor_sync(0xffffffffu, m, o));
        if (lane == 0) s_red[wp][s] = m;
    }
    __syncthreads();
    float mx[5];
#pragma unroll
    for (int s = 0; s < 5; s++) {
        float m = s_red[0][s];
#pragma unroll
        for (int w2 = 1; w2 < 8; w2++) m = fmaxf(m, s_red[w2][s]);
        mx[s] = m;
    }
    __syncthreads();

    float part[15];
#pragma unroll
    for (int s = 0; s < 5; s++) {
        float se = 0.f, sx = 0.f, sy = 0.f;
#pragma unroll
        for (int r = 0; r < 4; r++) {
            int p = tid + 256 * r;
            float e  = expf(l[s][r] - mx[s]);
            float xs = -1.f + (2.f / 31.f) * (float)(p & 31);
            float ys = -1.f + (2.f / 31.f) * (float)(p >> 5);
            se += e; sx += e * xs; sy += e * ys;
        }
        part[3 * s] = se; part[3 * s + 1] = sx; part[3 * s + 2] = sy;
    }
#pragma unroll
    for (int qq = 0; qq < 15; qq++)
#pragma unroll
        for (int o = 16; o; o >>= 1) part[qq] += __shfl_xor_sync(0xffffffffu, part[qq], o);
    if (lane == 0) {
#pragma unroll
        for (int qq = 0; qq < 15; qq++) s_red[wp][qq] = part[qq];
    }
    __syncthreads();
    if (tid < 5) {
        float se = 0.f, sx = 0.f, sy = 0.f;
        for (int w2 = 0; w2 < 8; w2++) {
            se += s_red[w2][3 * tid];
            sx += s_red[w2][3 * tid + 1];
            sy += s_red[w2][3 * tid + 2];
        }
        out[b * 10 + tid * 2 + 0] = sx / se;
        out[b * 10 + tid * 2 + 1] = sy / se;
    }
}

// ---------------- host-side stage driver ----------------
template<int S>
static void run_stage(const float* gw, const float* gb, const float* dw, const float* db) {
    constexpr int CIN = Cfg<S>::CIN, COUT = Cfg<S>::COUT, HIN = Cfg<S>::HIN;
    gn_norm_k<S><<<(BATCH * CIN) / 8, 256>>>(gw, gb);
    wtrans_all_k<S><<<(9 * CIN * COUT + 255) / 256, 256>>>(dw);
    constexpr int M = BATCH * HIN * HIN;
    dim3 g(M / 128, COUT / 64, 4);
    deconv_all_k<S><<<g, 256>>>(db);
}

extern "C" void kernel_launch(void* const* d_in, const int* in_sizes, int n_in,
                              void* d_out, int out_size) {
    (void)in_sizes; (void)n_in; (void)out_size;
    const float* feat   = (const float*)d_in[0];
    const int*   action = (const int*)  d_in[1];
    // d_in[2] = scene_idx (unused by reference)
    const float* fcw = (const float*)d_in[3];
    const float* fcb = (const float*)d_in[4];
    const float* gw0 = (const float*)d_in[5];  const float* gb0 = (const float*)d_in[6];
    const float* dw0 = (const float*)d_in[7];  const float* db0 = (const float*)d_in[8];
    const float* gw1 = (const float*)d_in[9];  const float* gb1 = (const float*)d_in[10];
    const float* dw1 = (const float*)d_in[11]; const float* db1 = (const float*)d_in[12];
    const float* gw2 = (const float*)d_in[13]; const float* gb2 = (const float*)d_in[14];
    const float* dw2 = (const float*)d_in[15]; const float* db2 = (const float*)d_in[16];
    const float* hgw = (const float*)d_in[17]; const float* hgb = (const float*)d_in[18];
    const float* hcw = (const float*)d_in[19]; const float* hcb = (const float*)d_in[20];
    float* out = (float*)d_out;

    fc_gemm_k<<<dim3(64, 8), 256>>>(feat, fcw, fcb);
    run_stage<0>(gw0, gb0, dw0, db0);
    run_stage<1>(gw1, gb1, dw1, db1);
    run_stage<2>(gw2, gb2, dw2, db2);
    head_k<<<BATCH, 256>>>(action, hgw, hgb, hcw, hcb, out);
}

// round 16
// speedup vs baseline: 1.5731x; 1.4821x over previous
#include <cuda_runtime.h>
#include <cuda_bf16.h>
#include <math.h>
#include <cstdint>

#define EPS 1e-5f
static constexpr int BATCH = 512;

// ---------------- scratch (static __device__ arrays; no allocation) ----------------
__device__ float g_x1[BATCH * 512 * 16];    // after FC+relu   (B,512,4,4)   -> gn in place
__device__ float g_x2[BATCH * 256 * 64];    // after stage0    (B,256,8,8)   -> gn in place
__device__ float g_x3[BATCH * 128 * 256];   // after stage1    (B,128,16,16) -> gn in place
__device__ float g_x4[BATCH * 64 * 1024];   // after stage2    (B,64,32,32)
__device__ float g_wq[9 * 512 * 256];       // per-quadrant transformed weights

// ---------------- per-stage config ----------------
template<int S> struct Cfg;
template<> struct Cfg<0> { static constexpr int CIN = 512, COUT = 256, HIN = 4;  };
template<> struct Cfg<1> { static constexpr int CIN = 256, COUT = 128, HIN = 8;  };
template<> struct Cfg<2> { static constexpr int CIN = 128, COUT = 64,  HIN = 16; };

template<int S> __device__ __forceinline__ float* in_ptr() {
    if constexpr (S == 0) return g_x1; else if constexpr (S == 1) return g_x2; else return g_x3;
}
template<int S> __device__ __forceinline__ float* out_ptr() {
    if constexpr (S == 0) return g_x2; else if constexpr (S == 1) return g_x3; else return g_x4;
}

// ---------------- bf16 split helpers ----------------
// x = hi + lo with hi,lo bf16 (~16-17 effective mantissa bits); lo*lo term dropped (~2^-16 rel)
__device__ __forceinline__ void bf16_split_pack(float x0, float x1, uint32_t& hi, uint32_t& lo) {
    __nv_bfloat16 h0 = __float2bfloat16(x0);
    __nv_bfloat16 h1 = __float2bfloat16(x1);
    __nv_bfloat16 l0 = __float2bfloat16(x0 - __bfloat162float(h0));
    __nv_bfloat16 l1 = __float2bfloat16(x1 - __bfloat162float(h1));
    hi = (uint32_t)__bfloat16_as_ushort(h0) | ((uint32_t)__bfloat16_as_ushort(h1) << 16);
    lo = (uint32_t)__bfloat16_as_ushort(l0) | ((uint32_t)__bfloat16_as_ushort(l1) << 16);
}
__device__ __forceinline__ void mma_bf16(float* c, const uint32_t* a, const uint32_t* b) {
    asm volatile(
        "mma.sync.aligned.m16n8k16.row.col.f32.bf16.bf16.f32 "
        "{%0,%1,%2,%3}, {%4,%5,%6,%7}, {%8,%9}, {%0,%1,%2,%3};\n"
        : "+f"(c[0]), "+f"(c[1]), "+f"(c[2]), "+f"(c[3])
        : "r"(a[0]), "r"(a[1]), "r"(a[2]), "r"(a[3]), "r"(b[0]), "r"(b[1]));
}

// packed-K tiles: row k2 = k/2 holds bf16x2 (k, k+1). stride mod 32 == 8 ->
// fragment bank = 8*tg + gi : perfect 32-way, conflict-free
#define AS_LD 136
#define BS_LD 72

// ---------------- FC (1x1 over channels) + ReLU : GEMM M=8192,N=512,K=256 (split-bf16) ----------------
__global__ void __launch_bounds__(256) fc_gemm_k(const float* __restrict__ feat,
                                                 const float* __restrict__ fcw,
                                                 const float* __restrict__ fcb) {
    __shared__ uint32_t AsH[8][AS_LD], AsL[8][AS_LD];
    __shared__ uint32_t BsH[8][BS_LD], BsL[8][BS_LD];
    const int tid = threadIdx.x;
    const int m0 = blockIdx.x * 128, n0 = blockIdx.y * 64;
    const int warp = tid >> 5, lane = tid & 31;
    const int wm = warp >> 1, wn = warp & 1;
    const int tg = lane & 3, gi = lane >> 2;

    float acc[2][4][4];
#pragma unroll
    for (int mt = 0; mt < 2; mt++)
#pragma unroll
        for (int nt = 0; nt < 4; nt++)
#pragma unroll
            for (int q = 0; q < 4; q++) acc[mt][nt][q] = 0.f;

    const int lm = tid & 127, lk0 = (tid >> 7) * 8;
    const int gm = m0 + lm;
    const int b  = gm >> 4, p = gm & 15;
    const float* fb = feat + (size_t)b * 256 * 16 + p;
    const int ln = tid & 63, lkb = (tid >> 6) * 4;
    const float* bptr = fcw + (size_t)lkb * 512 + n0 + ln;

    float pa[8], pb[4];
#pragma unroll
    for (int kk = 0; kk < 8; kk++) pa[kk] = fb[(lk0 + kk) * 16];
#pragma unroll
    for (int kk = 0; kk < 4; kk++) pb[kk] = bptr[(size_t)kk * 512];

    const int a0 = lk0 >> 1, b0r = lkb >> 1;
    for (int kc = 0; kc < 256; kc += 16) {
#pragma unroll
        for (int kk2 = 0; kk2 < 4; kk2++) {
            uint32_t h, l;
            bf16_split_pack(pa[2 * kk2], pa[2 * kk2 + 1], h, l);
            AsH[a0 + kk2][lm] = h; AsL[a0 + kk2][lm] = l;
        }
#pragma unroll
        for (int kk2 = 0; kk2 < 2; kk2++) {
            uint32_t h, l;
            bf16_split_pack(pb[2 * kk2], pb[2 * kk2 + 1], h, l);
            BsH[b0r + kk2][ln] = h; BsL[b0r + kk2][ln] = l;
        }
        __syncthreads();
        if (kc + 16 < 256) {
#pragma unroll
            for (int kk = 0; kk < 8; kk++) pa[kk] = fb[(kc + 16 + lk0 + kk) * 16];
            bptr += (size_t)16 * 512;
#pragma unroll
            for (int kk = 0; kk < 4; kk++) pb[kk] = bptr[(size_t)kk * 512];
        }
        {
            uint32_t ah[2][4], al[2][4], bh[4][2], bl[4][2];
#pragma unroll
            for (int mt = 0; mt < 2; mt++) {
                int r = wm * 32 + mt * 16 + gi;
                ah[mt][0] = AsH[tg][r];     al[mt][0] = AsL[tg][r];
                ah[mt][1] = AsH[tg][r + 8]; al[mt][1] = AsL[tg][r + 8];
                ah[mt][2] = AsH[tg + 4][r];     al[mt][2] = AsL[tg + 4][r];
                ah[mt][3] = AsH[tg + 4][r + 8]; al[mt][3] = AsL[tg + 4][r + 8];
            }
#pragma unroll
            for (int nt = 0; nt < 4; nt++) {
                int cN = wn * 32 + nt * 8 + gi;
                bh[nt][0] = BsH[tg][cN];     bl[nt][0] = BsL[tg][cN];
                bh[nt][1] = BsH[tg + 4][cN]; bl[nt][1] = BsL[tg + 4][cN];
            }
#pragma unroll
            for (int mt = 0; mt < 2; mt++)
#pragma unroll
                for (int nt = 0; nt < 4; nt++) {
                    mma_bf16(acc[mt][nt], al[mt], bh[nt]);
                    mma_bf16(acc[mt][nt], ah[mt], bl[nt]);
                    mma_bf16(acc[mt][nt], ah[mt], bh[nt]);
                }
        }
        __syncthreads();
    }
#pragma unroll
    for (int mt = 0; mt < 2; mt++)
#pragma unroll
        for (int half = 0; half < 2; half++) {
            int gm2 = m0 + wm * 32 + mt * 16 + gi + half * 8;
            int b2i = gm2 >> 4, p2 = gm2 & 15;
#pragma unroll
            for (int nt = 0; nt < 4; nt++) {
                int n = n0 + wn * 32 + nt * 8 + tg * 2;
                float v0 = acc[mt][nt][half * 2 + 0] + fcb[n];
                float v1 = acc[mt][nt][half * 2 + 1] + fcb[n + 1];
                g_x1[((size_t)b2i * 512 + n)     * 16 + p2] = fmaxf(v0, 0.f);
                g_x1[((size_t)b2i * 512 + n + 1) * 16 + p2] = fmaxf(v1, 0.f);
            }
        }
}

// ---------------- GroupNorm(dim,dim): warp per (b,c), normalize in place ----------------
template<int S>
__global__ void __launch_bounds__(256) gn_norm_k(const float* __restrict__ gamma,
                                                 const float* __restrict__ beta) {
    constexpr int C  = Cfg<S>::CIN;
    constexpr int HW = Cfg<S>::HIN * Cfg<S>::HIN;
    constexpr int NPER = (HW + 31) / 32;
    const int wid  = blockIdx.x * 8 + (threadIdx.x >> 5);
    const int lane = threadIdx.x & 31;
    const int c = wid & (C - 1);
    float* xp = in_ptr<S>() + (size_t)wid * HW;

    float v[NPER];
    float s = 0.f, sq = 0.f;
#pragma unroll
    for (int r = 0; r < NPER; r++) {
        int p = lane + 32 * r;
        float x = 0.f;
        if (HW % 32 == 0 || p < HW) x = xp[p];
        v[r] = x; s += x; sq += x * x;
    }
#pragma unroll
    for (int o = 16; o; o >>= 1) {
        s  += __shfl_xor_sync(0xffffffffu, s, o);
        sq += __shfl_xor_sync(0xffffffffu, sq, o);
    }
    const float inv = 1.f / (float)HW;
    float mu  = s * inv;
    float var = sq * inv - mu * mu;
    float rs  = rsqrtf(var + EPS);
    float sc  = gamma[c] * rs;
    float sh  = beta[c] - mu * sc;
#pragma unroll
    for (int r = 0; r < NPER; r++) {
        int p = lane + 32 * r;
        if (HW % 32 == 0 || p < HW) xp[p] = v[r] * sc + sh;
    }
}

// ---------------- weight transform (all 4 quadrants in one launch) ----------------
template<int S>
__global__ void wtrans_all_k(const float* __restrict__ w) {
    constexpr int CIN = Cfg<S>::CIN, COUT = Cfg<S>::COUT;
    constexpr int U = CIN * COUT;
    int idx = blockIdx.x * 256 + threadIdx.x;
    if (idx >= 9 * U) return;
    int PI, PJ, rel; size_t base;
    if (idx < U)          { PI = 0; PJ = 0; base = 0;             rel = idx;         }
    else if (idx < 3 * U) { PI = 0; PJ = 1; base = (size_t)U;     rel = idx - U;     }
    else if (idx < 5 * U) { PI = 1; PJ = 0; base = (size_t)3 * U; rel = idx - 3 * U; }
    else                  { PI = 1; PJ = 1; base = (size_t)5 * U; rel = idx - 5 * U; }
    int NC = PJ + 1, T = (PI + 1) * (PJ + 1);
    int k  = rel / COUT, co = rel - k * COUT;
    int ci = k / T, tap = k - ci * T;
    int tr = tap / NC, tc = tap - tr * NC;
    int kh = PI ? 2 * tr : 1;
    int kw = PJ ? 2 * tc : 1;
    g_wq[base + rel] = w[(size_t)(co * CIN + ci) * 9 + kh * 3 + kw];
}

// ---------------- fused deconv: all 4 quadrants via blockIdx.z (split-bf16 MMA) ----------------
// R13 skeleton: static smem, single buffer, register prefetch; bf16 k16 MMA halves
// both the MMA instruction count and the fragment LDS traffic.
template<int S>
__global__ void __launch_bounds__(256) deconv_all_k(const float* __restrict__ db) {
    constexpr int CIN = Cfg<S>::CIN, COUT = Cfg<S>::COUT, HIN = Cfg<S>::HIN;
    constexpr int HIN2 = HIN * HIN, HOUT = 2 * HIN;
    const int q  = blockIdx.z;                 // 0:(0,0) 1:(0,1) 2:(1,0) 3:(1,1)
    const int PI = q >> 1, PJ = q & 1;
    const int lt = PI + PJ;                    // log2(T): T = 1,2,2,4
    const int T  = 1 << lt;
    const int K  = CIN << lt;
    const size_t qbase = ((q == 0) ? 0 : (q == 1) ? 1 : (q == 2) ? 3 : 5) * (size_t)CIN * COUT;

    const float* __restrict__ xn = in_ptr<S>();
    float* __restrict__ out      = out_ptr<S>();
    const float* __restrict__ wq = g_wq + qbase;

    __shared__ uint32_t AsH[8][AS_LD], AsL[8][AS_LD];
    __shared__ uint32_t BsH[8][BS_LD], BsL[8][BS_LD];
    const int tid = threadIdx.x;
    const int m0 = blockIdx.x * 128, n0 = blockIdx.y * 64;
    const int warp = tid >> 5, lane = tid & 31;
    const int wm = warp >> 1, wn = warp & 1;
    const int tg = lane & 3, gi = lane >> 2;

    float acc[2][4][4];
#pragma unroll
    for (int mt = 0; mt < 2; mt++)
#pragma unroll
        for (int nt = 0; nt < 4; nt++)
#pragma unroll
            for (int qq = 0; qq < 4; qq++) acc[mt][nt][qq] = 0.f;

    const int lm = tid & 127, lk0 = (tid >> 7) * 8;
    const int gm = m0 + lm;
    const int bb = gm / HIN2, rr = gm & (HIN2 - 1);
    const int ii = rr / HIN,  jj = rr & (HIN - 1);
    const float* xb = xn + (size_t)bb * CIN * HIN2;
    const int ln = tid & 63, lkb = (tid >> 6) * 4;

    // hoisted gather offsets (affine in kc; T | 16)
    int off[8];
    unsigned vmask = 0;
#pragma unroll
    for (int kk = 0; kk < 8; kk++) {
        int k0 = lk0 + kk;
        int ci = k0 >> lt, tap = k0 & (T - 1);
        int tr = tap >> PJ, tc = tap & PJ;
        int ih = ii + (PI ? tr : 0);
        int iw = jj + (PJ ? tc : 0);
        bool ok = (!PI || ih < HIN) && (!PJ || iw < HIN);
        vmask |= (ok ? 1u : 0u) << kk;
        off[kk] = ci * HIN2 + ih * HIN + iw;
    }
    const int dA = (16 >> lt) * HIN2;
    const float* bptr = wq + (size_t)lkb * COUT + n0 + ln;

    float pa[8], pb[4];
#pragma unroll
    for (int kk = 0; kk < 8; kk++) {
        float v = 0.f;
        if ((vmask >> kk) & 1u) v = xb[off[kk]];
        pa[kk] = v; off[kk] += dA;
    }
#pragma unroll
    for (int kk = 0; kk < 4; kk++) pb[kk] = bptr[(size_t)kk * COUT];

    const int a0 = lk0 >> 1, b0r = lkb >> 1;
    const int nIter = K >> 4;
    for (int it = 0; it < nIter; it++) {
#pragma unroll
        for (int kk2 = 0; kk2 < 4; kk2++) {
            uint32_t h, l;
            bf16_split_pack(pa[2 * kk2], pa[2 * kk2 + 1], h, l);
            AsH[a0 + kk2][lm] = h; AsL[a0 + kk2][lm] = l;
        }
#pragma unroll
        for (int kk2 = 0; kk2 < 2; kk2++) {
            uint32_t h, l;
            bf16_split_pack(pb[2 * kk2], pb[2 * kk2 + 1], h, l);
            BsH[b0r + kk2][ln] = h; BsL[b0r + kk2][ln] = l;
        }
        __syncthreads();
        if (it + 1 < nIter) {
#pragma unroll
            for (int kk = 0; kk < 8; kk++) {
                float v = 0.f;
                if ((vmask >> kk) & 1u) v = xb[off[kk]];
                pa[kk] = v; off[kk] += dA;
            }
            bptr += (size_t)16 * COUT;
#pragma unroll
            for (int kk = 0; kk < 4; kk++) pb[kk] = bptr[(size_t)kk * COUT];
        }
        {
            uint32_t ah[2][4], al[2][4], bh[4][2], bl[4][2];
#pragma unroll
            for (int mt = 0; mt < 2; mt++) {
                int r = wm * 32 + mt * 16 + gi;
                ah[mt][0] = AsH[tg][r];     al[mt][0] = AsL[tg][r];
                ah[mt][1] = AsH[tg][r + 8]; al[mt][1] = AsL[tg][r + 8];
                ah[mt][2] = AsH[tg + 4][r];     al[mt][2] = AsL[tg + 4][r];
                ah[mt][3] = AsH[tg + 4][r + 8]; al[mt][3] = AsL[tg + 4][r + 8];
            }
#pragma unroll
            for (int nt = 0; nt < 4; nt++) {
                int cN = wn * 32 + nt * 8 + gi;
                bh[nt][0] = BsH[tg][cN];     bl[nt][0] = BsL[tg][cN];
                bh[nt][1] = BsH[tg + 4][cN]; bl[nt][1] = BsL[tg + 4][cN];
            }
#pragma unroll
            for (int mt = 0; mt < 2; mt++)
#pragma unroll
                for (int nt = 0; nt < 4; nt++) {
                    mma_bf16(acc[mt][nt], al[mt], bh[nt]);
                    mma_bf16(acc[mt][nt], ah[mt], bl[nt]);
                    mma_bf16(acc[mt][nt], ah[mt], bh[nt]);
                }
        }
        __syncthreads();
    }
#pragma unroll
    for (int mt = 0; mt < 2; mt++)
#pragma unroll
        for (int half = 0; half < 2; half++) {
            int gm2 = m0 + wm * 32 + mt * 16 + gi + half * 8;
            int b2i = gm2 / HIN2, r2 = gm2 & (HIN2 - 1);
            int oh = 2 * (r2 / HIN) + PI;
            int ow = 2 * (r2 & (HIN - 1)) + PJ;
            float* op = out + ((size_t)b2i * COUT * HOUT + oh) * HOUT + ow;
#pragma unroll
            for (int nt = 0; nt < 4; nt++) {
                int co = n0 + wn * 32 + nt * 8 + tg * 2;
                float v0 = acc[mt][nt][half * 2 + 0] + db[co];
                float v1 = acc[mt][nt][half * 2 + 1] + db[co + 1];
                op[(size_t)co       * HOUT * HOUT] = fmaxf(v0, 0.f);
                op[(size_t)(co + 1) * HOUT * HOUT] = fmaxf(v1, 0.f);
            }
        }
}

// ---------------- head: per-channel norm (folded) + 5-step GEMV + spatial softmax ----------------
__global__ void __launch_bounds__(256) head_k(const int* __restrict__ action,
                                              const float* __restrict__ hgw,
                                              const float* __restrict__ hgb,
                                              const float* __restrict__ hcw,
                                              const float* __restrict__ hcb,
                                              float* __restrict__ out) {
    const int b = blockIdx.x;
    const int tid = threadIdx.x;
    const int lane = tid & 31, wp = tid >> 5;
    __shared__ float s_mu[64], s_rs[64];
    __shared__ float s_ws[5][64];
    __shared__ float s_bias[5];
    __shared__ float s_red[8][15];

    const float* xb = g_x4 + (size_t)b * 64 * 1024;

    for (int c = wp; c < 64; c += 8) {
        const float* xc = xb + c * 1024;
        float s = 0.f, sq = 0.f;
        for (int p = lane; p < 1024; p += 32) { float v = xc[p]; s += v; sq += v * v; }
#pragma unroll
        for (int o = 16; o; o >>= 1) {
            s  += __shfl_xor_sync(0xffffffffu, s, o);
            sq += __shfl_xor_sync(0xffffffffu, sq, o);
        }
        if (lane == 0) {
            float mu = s * (1.f / 1024.f);
            float var = sq * (1.f / 1024.f) - mu * mu;
            s_mu[c] = mu;
            s_rs[c] = rsqrtf(var + EPS);
        }
    }
    __syncthreads();

    const int a = action[b];
    for (int idx = tid; idx < 320; idx += 256) {
        int s = idx >> 6, c = idx & 63;
        s_ws[s][c] = s_rs[c] * hcw[(a * 5 + s) * 64 + c] * hgw[a * 64 + c];
    }
    __syncthreads();
    if (tid < 5) {
        float acc = hcb[a * 5 + tid];
        for (int c = 0; c < 64; c++)
            acc += hcw[(a * 5 + tid) * 64 + c] * hgb[a * 64 + c] - s_mu[c] * s_ws[tid][c];
        s_bias[tid] = acc;
    }
    __syncthreads();

    float l[5][4];
#pragma unroll
    for (int s = 0; s < 5; s++)
#pragma unroll
        for (int r = 0; r < 4; r++) l[s][r] = 0.f;
    for (int c = 0; c < 64; c++) {
        float w0 = s_ws[0][c], w1 = s_ws[1][c], w2 = s_ws[2][c], w3 = s_ws[3][c], w4 = s_ws[4][c];
#pragma unroll
        for (int r = 0; r < 4; r++) {
            float xv = xb[c * 1024 + tid + 256 * r];
            l[0][r] += xv * w0; l[1][r] += xv * w1; l[2][r] += xv * w2;
            l[3][r] += xv * w3; l[4][r] += xv * w4;
        }
    }

#pragma unroll
    for (int s = 0; s < 5; s++) {
        float m = -1e30f;
#pragma unroll
        for (int r = 0; r < 4; r++) { l[s][r] += s_bias[s]; m = fmaxf(m, l[s][r]); }
#pragma unroll
        for (int o = 16; o; o >>= 1) m = fmaxf(m, __shfl_xor_sync(0xffffffffu, m, o));
        if (lane == 0) s_red[wp][s] = m;
    }
    __syncthreads();
    float mx[5];
#pragma unroll
    for (int s = 0; s < 5; s++) {
        float m = s_red[0][s];
#pragma unroll
        for (int w2 = 1; w2 < 8; w2++) m = fmaxf(m, s_red[w2][s]);
        mx[s] = m;
    }
    __syncthreads();

    float part[15];
#pragma unroll
    for (int s = 0; s < 5; s++) {
        float se = 0.f, sx = 0.f, sy = 0.f;
#pragma unroll
        for (int r = 0; r < 4; r++) {
            int p = tid + 256 * r;
            float e  = expf(l[s][r] - mx[s]);
            float xs = -1.f + (2.f / 31.f) * (float)(p & 31);
            float ys = -1.f + (2.f / 31.f) * (float)(p >> 5);
            se += e; sx += e * xs; sy += e * ys;
        }
        part[3 * s] = se; part[3 * s + 1] = sx; part[3 * s + 2] = sy;
    }
#pragma unroll
    for (int qq = 0; qq < 15; qq++)
#pragma unroll
        for (int o = 16; o; o >>= 1) part[qq] += __shfl_xor_sync(0xffffffffu, part[qq], o);
    if (lane == 0) {
#pragma unroll
        for (int qq = 0; qq < 15; qq++) s_red[wp][qq] = part[qq];
    }
    __syncthreads();
    if (tid < 5) {
        float se = 0.f, sx = 0.f, sy = 0.f;
        for (int w2 = 0; w2 < 8; w2++) {
            se += s_red[w2][3 * tid];
            sx += s_red[w2][3 * tid + 1];
            sy += s_red[w2][3 * tid + 2];
        }
        out[b * 10 + tid * 2 + 0] = sx / se;
        out[b * 10 + tid * 2 + 1] = sy / se;
    }
}

// ---------------- host-side stage driver ----------------
template<int S>
static void run_stage(const float* gw, const float* gb, const float* dw, const float* db) {
    constexpr int CIN = Cfg<S>::CIN, COUT = Cfg<S>::COUT, HIN = Cfg<S>::HIN;
    gn_norm_k<S><<<(BATCH * CIN) / 8, 256>>>(gw, gb);
    wtrans_all_k<S><<<(9 * CIN * COUT + 255) / 256, 256>>>(dw);
    constexpr int M = BATCH * HIN * HIN;
    dim3 g(M / 128, COUT / 64, 4);
    deconv_all_k<S><<<g, 256>>>(db);
}

extern "C" void kernel_launch(void* const* d_in, const int* in_sizes, int n_in,
                              void* d_out, int out_size) {
    (void)in_sizes; (void)n_in; (void)out_size;
    const float* feat   = (const float*)d_in[0];
    const int*   action = (const int*)  d_in[1];
    // d_in[2] = scene_idx (unused by reference)
    const float* fcw = (const float*)d_in[3];
    const float* fcb = (const float*)d_in[4];
    const float* gw0 = (const float*)d_in[5];  const float* gb0 = (const float*)d_in[6];
    const float* dw0 = (const float*)d_in[7];  const float* db0 = (const float*)d_in[8];
    const float* gw1 = (const float*)d_in[9];  const float* gb1 = (const float*)d_in[10];
    const float* dw1 = (const float*)d_in[11]; const float* db1 = (const float*)d_in[12];
    const float* gw2 = (const float*)d_in[13]; const float* gb2 = (const float*)d_in[14];
    const float* dw2 = (const float*)d_in[15]; const float* db2 = (const float*)d_in[16];
    const float* hgw = (const float*)d_in[17]; const float* hgb = (const float*)d_in[18];
    const float* hcw = (const float*)d_in[19]; const float* hcb = (const float*)d_in[20];
    float* out = (float*)d_out;

    fc_gemm_k<<<dim3(64, 8), 256>>>(feat, fcw, fcb);
    run_stage<0>(gw0, gb0, dw0, db0);
    run_stage<1>(gw1, gb1, dw1, db1);
    run_stage<2>(gw2, gb2, dw2, db2);
    head_k<<<BATCH, 256>>>(action, hgw, hgb, hcw, hcb, out);
}